// round 8
// baseline (speedup 1.0000x reference)
#include <cuda_runtime.h>
#include <cuda_bf16.h>
#include <cstdint>

// ============================================================================
// PNeRF coordinate extension as a chunked affine prefix scan (round 8).
// State (M, t): x_world = x_local @ M + t.  Step: M' = S M ; t' = t + bl*M'[0]
// Round 8: round-7 design with the elect-phase smem OOB fixed (guarded
//          cross-warp scan load, identity padding for lanes >= NW).
// ============================================================================

#define C1    12                 // atoms per chunk (per thread)
#define TPB   256                // chunks per block (8 warps)
#define NW    (TPB/32)
#define Q     (3*C1)             // 36 floats per chunk
#define ROWF  44                 // padded floats per row (176B; 44*12 mod 32 covers 8 banks)
#define ROW4  11                 // float4 per row
#define ROWU  9                  // used float4 per row (36 floats)
#define TILE_F (TPB*C1*3)        // 9216 floats per block tile
#define MAXCHUNKS 250112
#define MAXBLK    1024

struct Aff { float m[9]; float t[3]; };

__device__ float g_cs[12 * MAXCHUNKS];          // block-local inclusive chunk scans, SoA
__device__ float g_blockComp[MAXBLK * 12];
__device__ float g_basePrefix[MAXBLK * 12];
__device__ int   g_ctr;                          // zero-init; reset by elected block

// ---------------------------------------------------------------------------
// Accurate fp32 sincos (immune to --use_fast_math): Cody-Waite + Cephes polys.
// ---------------------------------------------------------------------------
__device__ __forceinline__ void fsincos(float x, float& s, float& c) {
    float q = rintf(x * 0.6366197723675814f);
    float r = fmaf(q, -1.5707963705062866f, x);
    r = fmaf(q, 4.37113883e-8f, r);
    int iq = (int)q;
    float z = r * r;
    float ps = fmaf(z, -1.9515295891e-4f, 8.3321608736e-3f);
    ps = fmaf(z, ps, -1.6666654611e-1f);
    float sr = fmaf(r * z, ps, r);
    float pc = fmaf(z, 2.443315711809948e-5f, -1.388731625493765e-3f);
    pc = fmaf(z, pc, 4.166664568298827e-2f);
    float cr = fmaf(z * z, pc, fmaf(z, -0.5f, 1.0f));
    bool sw = (iq & 1);
    float ss = sw ? cr : sr;
    float cc = sw ? sr : cr;
    if (iq & 2)        ss = -ss;
    if ((iq + 1) & 2)  cc = -cc;
    s = ss; c = cc;
}

// Theta path: bond_angle in [1.9, 2.1] -> Cody-Waite quadrant is always 1.
__device__ __forceinline__ void fsincos_th(float x, float& s, float& c) {
    float r = (x - 1.5707963705062866f) + 4.37113883e-8f;
    float z = r * r;
    float ps = fmaf(z, -1.9515295891e-4f, 8.3321608736e-3f);
    ps = fmaf(z, ps, -1.6666654611e-1f);
    float sr = fmaf(r * z, ps, r);
    float pc = fmaf(z, 2.443315711809948e-5f, -1.388731625493765e-3f);
    pc = fmaf(z, pc, 4.166664568298827e-2f);
    float cr = fmaf(z * z, pc, fmaf(z, -0.5f, 1.0f));
    s = cr; c = -sr;
}

__device__ __forceinline__ Aff aff_identity() {
    Aff a = {{1,0,0, 0,1,0, 0,0,1}, {0,0,0}};
    return a;
}

// Combine: A earlier (or state), B later composite.
__device__ __forceinline__ Aff cmb(const Aff& A, const Aff& B) {
    Aff r;
#pragma unroll
    for (int i = 0; i < 3; i++) {
        float b0 = B.m[3*i], b1 = B.m[3*i+1], b2 = B.m[3*i+2];
#pragma unroll
        for (int j = 0; j < 3; j++)
            r.m[3*i+j] = fmaf(b0, A.m[j], fmaf(b1, A.m[3+j], b2 * A.m[6+j]));
    }
#pragma unroll
    for (int j = 0; j < 3; j++)
        r.t[j] = fmaf(B.t[0], A.m[j], fmaf(B.t[1], A.m[3+j],
                 fmaf(B.t[2], A.m[6+j], A.t[j])));
    return r;
}

__device__ __forceinline__ void chain_step(float bl, float th, float ph, Aff& s) {
    float st, ct, sp, cp;
    fsincos_th(th, st, ct);
    fsincos(ph, sp, cp);
    float a = cp * st, b = sp * st, c = cp * ct, d = sp * ct;
#pragma unroll
    for (int j = 0; j < 3; j++) {
        float m0 = s.m[j], m1 = s.m[3+j], m2 = s.m[6+j];
        float r0 = fmaf(ct, m0, fmaf(a, m1, b * m2));
        float r1 = fmaf(c,  m1, fmaf(d, m2, -st * m0));
        float r2 = fmaf(cp, m2, -sp * m1);
        s.m[j] = r0; s.m[3+j] = r1; s.m[6+j] = r2;
        s.t[j] = fmaf(bl, r0, s.t[j]);
    }
}

// First step from identity: s = S, t = bl*S[0].
__device__ __forceinline__ void first_step(float bl, float th, float ph, Aff& s) {
    float st, ct, sp, cp;
    fsincos_th(th, st, ct);
    fsincos(ph, sp, cp);
    s.m[0] = ct;        s.m[1] = cp*st;  s.m[2] = sp*st;
    s.m[3] = -st;       s.m[4] = cp*ct;  s.m[5] = sp*ct;
    s.m[6] = 0.0f;      s.m[7] = -sp;    s.m[8] = cp;
    s.t[0] = bl*s.m[0]; s.t[1] = bl*s.m[1]; s.t[2] = bl*s.m[2];
}

__device__ __forceinline__ void reortho(Aff& s) {
    float inv = rsqrtf(fmaf(s.m[0], s.m[0], fmaf(s.m[1], s.m[1], s.m[2]*s.m[2])));
    s.m[0] *= inv; s.m[1] *= inv; s.m[2] *= inv;
    float d = fmaf(s.m[6], s.m[0], fmaf(s.m[7], s.m[1], s.m[8]*s.m[2]));
    s.m[6] = fmaf(-d, s.m[0], s.m[6]);
    s.m[7] = fmaf(-d, s.m[1], s.m[7]);
    s.m[8] = fmaf(-d, s.m[2], s.m[8]);
    inv = rsqrtf(fmaf(s.m[6], s.m[6], fmaf(s.m[7], s.m[7], s.m[8]*s.m[8])));
    s.m[6] *= inv; s.m[7] *= inv; s.m[8] *= inv;
    s.m[3] = s.m[7]*s.m[2] - s.m[8]*s.m[1];
    s.m[4] = s.m[8]*s.m[0] - s.m[6]*s.m[2];
    s.m[5] = s.m[6]*s.m[1] - s.m[7]*s.m[0];
}

__device__ __forceinline__ void aff_store(float* p, const Aff& a) {
#pragma unroll
    for (int i = 0; i < 9; i++) p[i] = a.m[i];
#pragma unroll
    for (int i = 0; i < 3; i++) p[9+i] = a.t[i];
}
__device__ __forceinline__ Aff aff_load(const float* p) {
    Aff a;
#pragma unroll
    for (int i = 0; i < 9; i++) a.m[i] = p[i];
#pragma unroll
    for (int i = 0; i < 3; i++) a.t[i] = p[9+i];
    return a;
}

__device__ __forceinline__ Aff aff_shfl_up(const Aff& a, int delta) {
    Aff r;
#pragma unroll
    for (int i = 0; i < 9; i++) r.m[i] = __shfl_up_sync(0xffffffffu, a.m[i], delta);
#pragma unroll
    for (int i = 0; i < 3; i++) r.t[i] = __shfl_up_sync(0xffffffffu, a.t[i], delta);
    return r;
}

// Frame of mainchain[:3] as an Aff.
__device__ __forceinline__ Aff frame0(const float* __restrict__ mc) {
    float Ax = mc[0], Ay = mc[1], Az = mc[2];
    float Bx = mc[3], By = mc[4], Bz = mc[5];
    float Cx = mc[6], Cy = mc[7], Cz = mc[8];
    float bx = Cx-Bx, by = Cy-By, bz = Cz-Bz;
    float inv = rsqrtf(bx*bx + by*by + bz*bz);
    bx *= inv; by *= inv; bz *= inv;
    float ux = Bx-Ax, uy = By-Ay, uz = Bz-Az;
    float nx = uy*bz - uz*by, ny = uz*bx - ux*bz, nz = ux*by - uy*bx;
    inv = rsqrtf(nx*nx + ny*ny + nz*nz);
    nx *= inv; ny *= inv; nz *= inv;
    Aff s0;
    s0.m[0]=bx; s0.m[1]=by; s0.m[2]=bz;
    s0.m[3]=ny*bz - nz*by; s0.m[4]=nz*bx - nx*bz; s0.m[5]=nx*by - ny*bx;
    s0.m[6]=nx; s0.m[7]=ny; s0.m[8]=nz;
    s0.t[0]=Cx; s0.t[1]=Cy; s0.t[2]=Cz;
    return s0;
}

// Stage a block tile into padded rows: float f -> st[(f/Q)*ROWF + f%Q].
__device__ __forceinline__ void stage_in(float* st, const float* __restrict__ gin,
                                          int nfl, int tid) {
    if (nfl == TILE_F) {
        const float4* g4 = (const float4*)gin;
        float4* s4 = (float4*)st;
#pragma unroll
        for (int it = 0; it < TILE_F/4/TPB; it++) {     // 9
            int idx = tid + it*TPB;                      // < 2304
            int j = idx / ROWU, k = idx - ROWU * (idx / ROWU);
            s4[j*ROW4 + k] = g4[idx];
        }
    } else {
        for (int f = tid; f < nfl; f += TPB) {
            int j = f / Q, q = f - Q * (f / Q);
            st[j*ROWF + q] = gin[f];
        }
    }
}

// ---------------------------------------------------------------------------
// K1: stage, walk chunk composites, block scan, SoA store; last-done block
//     performs the cross-block scan (old k2) with 256 threads.
// ---------------------------------------------------------------------------
__global__ void __launch_bounds__(TPB, 5) k1_chunks(
        const float* __restrict__ inner, const float* __restrict__ mc,
        float* __restrict__ out, int n, int nchunks, int nb) {
    __shared__ float st[TPB * ROWF];    // 45056 B
    __shared__ float swc[NW * 12];
    __shared__ int elect;
    int tid = threadIdx.x, b = blockIdx.x;
    int lane = tid & 31, wid = tid >> 5;
    int chunk = b * TPB + tid;

    long long tile0 = (long long)b * TILE_F;
    int nfl = (int)min((long long)TILE_F, (long long)n * 3 - tile0);
    stage_in(st, inner + tile0, nfl, tid);
    __syncthreads();

    Aff s = aff_identity();
    if (chunk < nchunks) {
        int base = chunk * C1;
        if (base + C1 <= n) {
            const float4* row4 = (const float4*)st + tid * ROW4;
            float4 va = row4[0], vb = row4[1], vc = row4[2];
            first_step(va.x, va.y, va.z, s);
            chain_step(va.w, vb.x, vb.y, s);
            chain_step(vb.z, vb.w, vc.x, s);
            chain_step(vc.y, vc.z, vc.w, s);
#pragma unroll
            for (int G = 1; G < 3; G++) {
                va = row4[3*G]; vb = row4[3*G+1]; vc = row4[3*G+2];
                chain_step(va.x, va.y, va.z, s);
                chain_step(va.w, vb.x, vb.y, s);
                chain_step(vb.z, vb.w, vc.x, s);
                chain_step(vc.y, vc.z, vc.w, s);
            }
        } else {
            int lim = n - base;
            const float* col = st + tid * ROWF;
            if (lim > 0) first_step(col[0], col[1], col[2], s);
            for (int k = 1; k < lim; k++)
                chain_step(col[3*k], col[3*k+1], col[3*k+2], s);
        }
    }
    // block scan (warp shuffle + cross-warp)
#pragma unroll
    for (int off = 1; off < 32; off <<= 1) {
        Aff p = aff_shfl_up(s, off);
        if (lane >= off) s = cmb(p, s);
    }
    if (lane == 31) aff_store(&swc[wid*12], s);
    __syncthreads();
    if (wid == 0) {
        Aff w = (lane < NW) ? aff_load(&swc[lane*12]) : aff_identity();
#pragma unroll
        for (int off = 1; off < NW; off <<= 1) {
            Aff p = aff_shfl_up(w, off);
            if (lane >= off) w = cmb(p, w);
        }
        if (lane < NW) aff_store(&swc[lane*12], w);
    }
    __syncthreads();
    if (wid > 0) s = cmb(aff_load(&swc[(wid-1)*12]), s);

    if (chunk < nchunks) {
#pragma unroll
        for (int c = 0; c < 9; c++)  g_cs[c*MAXCHUNKS + chunk] = s.m[c];
#pragma unroll
        for (int c = 0; c < 3; c++)  g_cs[(9+c)*MAXCHUNKS + chunk] = s.t[c];
    }
    if (tid == TPB - 1) aff_store(&g_blockComp[b*12], s);

    // ---- last-done election: the final block runs the cross-block scan ----
    __threadfence();
    __syncthreads();
    if (tid == 0) {
        int old = atomicAdd(&g_ctr, 1);
        elect = (old == (int)gridDim.x - 1) ? 1 : 0;
    }
    __syncthreads();
    if (!elect) return;
    __threadfence();                       // acquire: see all blocks' composites

    if (tid < 9) out[tid] = mc[tid];       // frame0 rows

    // serial compose 4 entries per thread (raw, no reortho)
    Aff c4 = aff_identity();
    int e0 = 4 * tid;
#pragma unroll
    for (int i = 0; i < 4; i++) {
        int j = e0 + i;
        if (j < nb) c4 = cmb(c4, aff_load(&g_blockComp[j*12]));
    }
    __syncthreads();                       // swc reuse: block-scan phase done
    // 256-thread shuffle scan of the 4-entry composites
    Aff sc = c4;
#pragma unroll
    for (int off = 1; off < 32; off <<= 1) {
        Aff p = aff_shfl_up(sc, off);
        if (lane >= off) sc = cmb(p, sc);
    }
    if (lane == 31) aff_store(&swc[wid*12], sc);
    __syncthreads();
    if (wid == 0) {
        // GUARDED: swc holds only NW entries; identity-pad lanes >= NW.
        Aff w = (lane < NW) ? aff_load(&swc[lane*12]) : aff_identity();
#pragma unroll
        for (int off = 1; off < NW; off <<= 1) {
            Aff p = aff_shfl_up(w, off);
            if (lane >= off) w = cmb(p, w);
        }
        if (lane < NW) aff_store(&swc[lane*12], w);
    }
    __syncthreads();
    if (wid > 0) sc = cmb(aff_load(&swc[(wid-1)*12]), sc);   // inclusive
    Aff E = aff_shfl_up(sc, 1);                               // exclusive
    if (lane == 0 && wid > 0) E = aff_load(&swc[(wid-1)*12]);

    Aff s0 = frame0(mc);
    Aff run = (tid == 0) ? s0 : cmb(s0, E);
#pragma unroll
    for (int i = 0; i < 4; i++) {
        int j = e0 + i;
        if (j < nb) {
            Aff bp = run;
            reortho(bp);
            aff_store(&g_basePrefix[j*12], bp);
            run = cmb(run, aff_load(&g_blockComp[j*12]));
        }
    }
    if (tid == 0) g_ctr = 0;               // reset for next graph replay
}

// ---------------------------------------------------------------------------
// K3: stage, seed from prefix, walk with in-place float4 write-back,
//     vectorized flush ((out+9+tile0)+3 is 16B-aligned).
// ---------------------------------------------------------------------------
__global__ void __launch_bounds__(TPB, 5) k3_emit(
        const float* __restrict__ inner, int n, int nchunks,
        float* __restrict__ out) {
    __shared__ float st[TPB * ROWF];
    int tid = threadIdx.x, b = blockIdx.x;
    int chunk = b * TPB + tid;

    long long tile0 = (long long)b * TILE_F;
    int nfl = (int)min((long long)TILE_F, (long long)n * 3 - tile0);
    stage_in(st, inner + tile0, nfl, tid);
    __syncthreads();

    if (chunk < nchunks) {
        Aff s = aff_load(&g_basePrefix[b*12]);
        if (tid > 0) {
            Aff pre;
#pragma unroll
            for (int c = 0; c < 9; c++) pre.m[c] = g_cs[c*MAXCHUNKS + chunk - 1];
#pragma unroll
            for (int c = 0; c < 3; c++) pre.t[c] = g_cs[(9+c)*MAXCHUNKS + chunk - 1];
            s = cmb(s, pre);
        }
        reortho(s);
        int base = chunk * C1;
        if (base + C1 <= n) {
            float4* row4 = (float4*)st + tid * ROW4;
#pragma unroll
            for (int G = 0; G < 3; G++) {
                float4 va = row4[3*G], vb = row4[3*G+1], vc = row4[3*G+2];
                float4 oa, ob, oc;
                chain_step(va.x, va.y, va.z, s); oa.x=s.t[0]; oa.y=s.t[1]; oa.z=s.t[2];
                chain_step(va.w, vb.x, vb.y, s); oa.w=s.t[0]; ob.x=s.t[1]; ob.y=s.t[2];
                chain_step(vb.z, vb.w, vc.x, s); ob.z=s.t[0]; ob.w=s.t[1]; oc.x=s.t[2];
                chain_step(vc.y, vc.z, vc.w, s); oc.y=s.t[0]; oc.z=s.t[1]; oc.w=s.t[2];
                row4[3*G] = oa; row4[3*G+1] = ob; row4[3*G+2] = oc;
            }
        } else {
            int lim = n - base;
            float* col = st + tid * ROWF;
            for (int k = 0; k < lim; k++) {
                chain_step(col[3*k], col[3*k+1], col[3*k+2], s);
                col[3*k]   = s.t[0];
                col[3*k+1] = s.t[1];
                col[3*k+2] = s.t[2];
            }
        }
    }
    __syncthreads();

    float* gout = out + 9 + tile0;
    if (nfl == TILE_F) {
        // head: floats 0..2 live in row 0, q 0..2
        if (tid < 3) gout[tid] = st[tid];
        // tail: float 9215 = row 255, q 35
        if (tid == 3) gout[TILE_F-1] = st[(TPB-1)*ROWF + Q - 1];
        // body: float4 m covers floats 3+4m .. 6+4m;  (gout+3) is 16B-aligned
        float4* g4 = (float4*)(gout + 3);
#pragma unroll 3
        for (int m = tid; m < (TILE_F-4)/4; m += TPB) {   // m < 2303
            int f0 = 3 + 4*m;                              // f0 % 4 == 3 -> q in {3,7,...,35}
            int j = f0 / Q, q = f0 - Q * (f0 / Q);
            const float* r = st + j*ROWF + q;
            float4 v;
            if (q < Q - 1) { v.x = r[0]; v.y = r[1]; v.z = r[2]; v.w = r[3]; }
            else {          // q == 35: spans row boundary
                const float* r2 = st + (j+1)*ROWF;
                v.x = r[0]; v.y = r2[0]; v.z = r2[1]; v.w = r2[2];
            }
            g4[m] = v;
        }
    } else {
        for (int f = tid; f < nfl; f += TPB) {
            int j = f / Q, q = f - Q * (f / Q);
            gout[f] = st[j*ROWF + q];
        }
    }
}

extern "C" void kernel_launch(void* const* d_in, const int* in_sizes, int n_in,
                              void* d_out, int out_size) {
    const float* inner = (const float*)d_in[0];
    const float* mc    = (const float*)d_in[2];
    float* out = (float*)d_out;
    int n = in_sizes[0] / 3;
    int nchunks = (n + C1 - 1) / C1;              // 250000
    int nblocks = (nchunks + TPB - 1) / TPB;      // 977  (<= 1024)

    k1_chunks<<<nblocks, TPB>>>(inner, mc, out, n, nchunks, nblocks);
    k3_emit<<<nblocks, TPB>>>(inner, n, nchunks, out);
}

// round 9
// speedup vs baseline: 1.1412x; 1.1412x over previous
#include <cuda_runtime.h>
#include <cuda_bf16.h>
#include <cstdint>

// ============================================================================
// PNeRF coordinate extension as a chunked affine prefix scan (round 9).
// State (M, t): x_world = x_local @ M + t.  Step: M' = S M ; t' = t + bl*M'[0]
// Round 9: revert to the proven R6 tile (C1=16/TPB=192/ROWF=52, division-free
//          index math, conflict-free .128 smem); keep only the validated
//          last-block-done fusion of the cross-block scan into k1.
// ============================================================================

#define C1    16                 // atoms per chunk (per thread)
#define TPB   192                // chunks per block (6 warps)
#define NW    (TPB/32)
#define Q     (3*C1)             // 48 floats per chunk
#define ROWF  52                 // padded floats per row (208B, 16B-aligned, conflict-free .128)
#define ROW4  13                 // float4 per row
#define TILE_F (TPB*C1*3)        // 9216 floats per block tile
#define MAXCHUNKS 188160
#define MAXBLK    1024
#define EPT   6                  // cross-block scan entries per thread (192*6=1152 >= 977)

struct Aff { float m[9]; float t[3]; };

__device__ float g_cs[12 * MAXCHUNKS];          // chunkScan, SoA: [comp][chunk]
__device__ float g_blockComp[MAXBLK * 12];
__device__ float g_basePrefix[MAXBLK * 12];
__device__ int   g_ctr;                          // zero-init; reset by elected block

// ---------------------------------------------------------------------------
// Accurate fp32 sincos (immune to --use_fast_math): Cody-Waite + Cephes polys.
// ---------------------------------------------------------------------------
__device__ __forceinline__ void fsincos(float x, float& s, float& c) {
    float q = rintf(x * 0.6366197723675814f);
    float r = fmaf(q, -1.5707963705062866f, x);
    r = fmaf(q, 4.37113883e-8f, r);
    int iq = (int)q;
    float z = r * r;
    float ps = fmaf(z, -1.9515295891e-4f, 8.3321608736e-3f);
    ps = fmaf(z, ps, -1.6666654611e-1f);
    float sr = fmaf(r * z, ps, r);
    float pc = fmaf(z, 2.443315711809948e-5f, -1.388731625493765e-3f);
    pc = fmaf(z, pc, 4.166664568298827e-2f);
    float cr = fmaf(z * z, pc, fmaf(z, -0.5f, 1.0f));
    bool sw = (iq & 1);
    float ss = sw ? cr : sr;
    float cc = sw ? sr : cr;
    if (iq & 2)        ss = -ss;
    if ((iq + 1) & 2)  cc = -cc;
    s = ss; c = cc;
}

// Theta path: bond_angle in [1.9, 2.1] -> Cody-Waite quadrant is always 1.
__device__ __forceinline__ void fsincos_th(float x, float& s, float& c) {
    float r = (x - 1.5707963705062866f) + 4.37113883e-8f;
    float z = r * r;
    float ps = fmaf(z, -1.9515295891e-4f, 8.3321608736e-3f);
    ps = fmaf(z, ps, -1.6666654611e-1f);
    float sr = fmaf(r * z, ps, r);
    float pc = fmaf(z, 2.443315711809948e-5f, -1.388731625493765e-3f);
    pc = fmaf(z, pc, 4.166664568298827e-2f);
    float cr = fmaf(z * z, pc, fmaf(z, -0.5f, 1.0f));
    s = cr; c = -sr;
}

__device__ __forceinline__ Aff aff_identity() {
    Aff a = {{1,0,0, 0,1,0, 0,0,1}, {0,0,0}};
    return a;
}

// Combine: A earlier (or state), B later composite.
__device__ __forceinline__ Aff cmb(const Aff& A, const Aff& B) {
    Aff r;
#pragma unroll
    for (int i = 0; i < 3; i++) {
        float b0 = B.m[3*i], b1 = B.m[3*i+1], b2 = B.m[3*i+2];
#pragma unroll
        for (int j = 0; j < 3; j++)
            r.m[3*i+j] = fmaf(b0, A.m[j], fmaf(b1, A.m[3+j], b2 * A.m[6+j]));
    }
#pragma unroll
    for (int j = 0; j < 3; j++)
        r.t[j] = fmaf(B.t[0], A.m[j], fmaf(B.t[1], A.m[3+j],
                 fmaf(B.t[2], A.m[6+j], A.t[j])));
    return r;
}

__device__ __forceinline__ void chain_step(float bl, float th, float ph, Aff& s) {
    float st, ct, sp, cp;
    fsincos_th(th, st, ct);
    fsincos(ph, sp, cp);
    float a = cp * st, b = sp * st, c = cp * ct, d = sp * ct;
#pragma unroll
    for (int j = 0; j < 3; j++) {
        float m0 = s.m[j], m1 = s.m[3+j], m2 = s.m[6+j];
        float r0 = fmaf(ct, m0, fmaf(a, m1, b * m2));
        float r1 = fmaf(c,  m1, fmaf(d, m2, -st * m0));
        float r2 = fmaf(cp, m2, -sp * m1);
        s.m[j] = r0; s.m[3+j] = r1; s.m[6+j] = r2;
        s.t[j] = fmaf(bl, r0, s.t[j]);
    }
}

// First step from identity: s = S, t = bl*S[0].
__device__ __forceinline__ void first_step(float bl, float th, float ph, Aff& s) {
    float st, ct, sp, cp;
    fsincos_th(th, st, ct);
    fsincos(ph, sp, cp);
    s.m[0] = ct;        s.m[1] = cp*st;  s.m[2] = sp*st;
    s.m[3] = -st;       s.m[4] = cp*ct;  s.m[5] = sp*ct;
    s.m[6] = 0.0f;      s.m[7] = -sp;    s.m[8] = cp;
    s.t[0] = bl*s.m[0]; s.t[1] = bl*s.m[1]; s.t[2] = bl*s.m[2];
}

__device__ __forceinline__ void reortho(Aff& s) {
    float inv = rsqrtf(fmaf(s.m[0], s.m[0], fmaf(s.m[1], s.m[1], s.m[2]*s.m[2])));
    s.m[0] *= inv; s.m[1] *= inv; s.m[2] *= inv;
    float d = fmaf(s.m[6], s.m[0], fmaf(s.m[7], s.m[1], s.m[8]*s.m[2]));
    s.m[6] = fmaf(-d, s.m[0], s.m[6]);
    s.m[7] = fmaf(-d, s.m[1], s.m[7]);
    s.m[8] = fmaf(-d, s.m[2], s.m[8]);
    inv = rsqrtf(fmaf(s.m[6], s.m[6], fmaf(s.m[7], s.m[7], s.m[8]*s.m[8])));
    s.m[6] *= inv; s.m[7] *= inv; s.m[8] *= inv;
    s.m[3] = s.m[7]*s.m[2] - s.m[8]*s.m[1];
    s.m[4] = s.m[8]*s.m[0] - s.m[6]*s.m[2];
    s.m[5] = s.m[6]*s.m[1] - s.m[7]*s.m[0];
}

__device__ __forceinline__ void aff_store(float* p, const Aff& a) {
#pragma unroll
    for (int i = 0; i < 9; i++) p[i] = a.m[i];
#pragma unroll
    for (int i = 0; i < 3; i++) p[9+i] = a.t[i];
}
__device__ __forceinline__ Aff aff_load(const float* p) {
    Aff a;
#pragma unroll
    for (int i = 0; i < 9; i++) a.m[i] = p[i];
#pragma unroll
    for (int i = 0; i < 3; i++) a.t[i] = p[9+i];
    return a;
}

__device__ __forceinline__ Aff aff_shfl_up(const Aff& a, int delta) {
    Aff r;
#pragma unroll
    for (int i = 0; i < 9; i++) r.m[i] = __shfl_up_sync(0xffffffffu, a.m[i], delta);
#pragma unroll
    for (int i = 0; i < 3; i++) r.t[i] = __shfl_up_sync(0xffffffffu, a.t[i], delta);
    return r;
}

// Frame of mainchain[:3] as an Aff.
__device__ __forceinline__ Aff frame0(const float* __restrict__ mc) {
    float Ax = mc[0], Ay = mc[1], Az = mc[2];
    float Bx = mc[3], By = mc[4], Bz = mc[5];
    float Cx = mc[6], Cy = mc[7], Cz = mc[8];
    float bx = Cx-Bx, by = Cy-By, bz = Cz-Bz;
    float inv = rsqrtf(bx*bx + by*by + bz*bz);
    bx *= inv; by *= inv; bz *= inv;
    float ux = Bx-Ax, uy = By-Ay, uz = Bz-Az;
    float nx = uy*bz - uz*by, ny = uz*bx - ux*bz, nz = ux*by - uy*bx;
    inv = rsqrtf(nx*nx + ny*ny + nz*nz);
    nx *= inv; ny *= inv; nz *= inv;
    Aff s0;
    s0.m[0]=bx; s0.m[1]=by; s0.m[2]=bz;
    s0.m[3]=ny*bz - nz*by; s0.m[4]=nz*bx - nx*bz; s0.m[5]=nx*by - ny*bx;
    s0.m[6]=nx; s0.m[7]=ny; s0.m[8]=nz;
    s0.t[0]=Cx; s0.t[1]=Cy; s0.t[2]=Cz;
    return s0;
}

// Stage a block tile into padded linear rows: st[(f/Q)*ROWF + f%Q].
// Full-tile fast path: float4 copy; j advances by exactly 16 per iteration
// (TPB/12 == 16), k invariant. Division-free inner loop.
__device__ __forceinline__ void stage_in(float* st, const float* __restrict__ gin,
                                          int nfl, int tid) {
    if (nfl == TILE_F) {
        const float4* g4 = (const float4*)gin;
        float4* s4 = (float4*)st;
        int j0 = tid / 12, k0 = tid - 12 * (tid / 12);
        int dst = j0 * ROW4 + k0;
#pragma unroll
        for (int it = 0; it < TILE_F/4/TPB; it++) {     // 12
            s4[dst] = g4[tid + it*TPB];
            dst += 16 * ROW4;
        }
    } else {
        int q0 = tid % Q, j0 = tid / Q;
        for (int f = tid; f < nfl; f += TPB) {
            st[j0*ROWF + q0] = gin[f];
            j0 += TPB/Q;
        }
    }
}

// ---------------------------------------------------------------------------
// K1: stage, walk chunk composites (vector), block scan, SoA store; last-done
//     block performs the cross-block scan with its 192 threads.
// ---------------------------------------------------------------------------
__global__ void __launch_bounds__(TPB) k1_chunks(
        const float* __restrict__ inner, const float* __restrict__ mc,
        float* __restrict__ out, int n, int nchunks, int nb) {
    __shared__ float st[TPB * ROWF];    // 39936 B
    __shared__ float swc[NW * 12];
    __shared__ int elect;
    int tid = threadIdx.x, b = blockIdx.x;
    int lane = tid & 31, wid = tid >> 5;
    int chunk = b * TPB + tid;

    long long tile0 = (long long)b * TILE_F;
    int nfl = (int)min((long long)TILE_F, (long long)n * 3 - tile0);
    stage_in(st, inner + tile0, nfl, tid);
    __syncthreads();

    Aff s = aff_identity();
    if (chunk < nchunks) {
        int base = chunk * C1;
        if (base + C1 <= n) {
            const float4* row4 = (const float4*)st + tid * ROW4;
            float4 va = row4[0], vb = row4[1], vc = row4[2];
            first_step(va.x, va.y, va.z, s);
            chain_step(va.w, vb.x, vb.y, s);
            chain_step(vb.z, vb.w, vc.x, s);
            chain_step(vc.y, vc.z, vc.w, s);
#pragma unroll
            for (int G = 1; G < 4; G++) {
                va = row4[3*G]; vb = row4[3*G+1]; vc = row4[3*G+2];
                chain_step(va.x, va.y, va.z, s);
                chain_step(va.w, vb.x, vb.y, s);
                chain_step(vb.z, vb.w, vc.x, s);
                chain_step(vc.y, vc.z, vc.w, s);
            }
        } else {
            int lim = n - base;
            const float* col = st + tid * ROWF;
            if (lim > 0) first_step(col[0], col[1], col[2], s);
            for (int k = 1; k < lim; k++)
                chain_step(col[3*k], col[3*k+1], col[3*k+2], s);
        }
    }
    // block scan (warp shuffle + cross-warp)
#pragma unroll
    for (int off = 1; off < 32; off <<= 1) {
        Aff p = aff_shfl_up(s, off);
        if (lane >= off) s = cmb(p, s);
    }
    if (lane == 31) aff_store(&swc[wid*12], s);
    __syncthreads();
    if (wid == 0) {
        Aff w = (lane < NW) ? aff_load(&swc[lane*12]) : aff_identity();
#pragma unroll
        for (int off = 1; off < NW; off <<= 1) {
            Aff p = aff_shfl_up(w, off);
            if (lane >= off) w = cmb(p, w);
        }
        if (lane < NW) aff_store(&swc[lane*12], w);
    }
    __syncthreads();
    if (wid > 0) s = cmb(aff_load(&swc[(wid-1)*12]), s);

    if (chunk < nchunks) {
#pragma unroll
        for (int c = 0; c < 9; c++)  g_cs[c*MAXCHUNKS + chunk] = s.m[c];
#pragma unroll
        for (int c = 0; c < 3; c++)  g_cs[(9+c)*MAXCHUNKS + chunk] = s.t[c];
    }
    if (tid == TPB - 1) aff_store(&g_blockComp[b*12], s);

    // ---- last-done election: the final block runs the cross-block scan ----
    __threadfence();
    __syncthreads();
    if (tid == 0) {
        int old = atomicAdd(&g_ctr, 1);
        elect = (old == (int)gridDim.x - 1) ? 1 : 0;
    }
    __syncthreads();
    if (!elect) return;
    __threadfence();                       // acquire: see all blocks' composites

    if (tid < 9) out[tid] = mc[tid];       // frame0 rows

    // serial compose EPT entries per thread (raw, no reortho)
    Aff c6 = aff_identity();
    int e0 = EPT * tid;
#pragma unroll
    for (int i = 0; i < EPT; i++) {
        int j = e0 + i;
        if (j < nb) c6 = cmb(c6, aff_load(&g_blockComp[j*12]));
    }
    __syncthreads();                       // swc reuse: block-scan phase done
    // 192-thread shuffle scan of the EPT-entry composites
    Aff sc = c6;
#pragma unroll
    for (int off = 1; off < 32; off <<= 1) {
        Aff p = aff_shfl_up(sc, off);
        if (lane >= off) sc = cmb(p, sc);
    }
    if (lane == 31) aff_store(&swc[wid*12], sc);
    __syncthreads();
    if (wid == 0) {
        Aff w = (lane < NW) ? aff_load(&swc[lane*12]) : aff_identity();
#pragma unroll
        for (int off = 1; off < NW; off <<= 1) {
            Aff p = aff_shfl_up(w, off);
            if (lane >= off) w = cmb(p, w);
        }
        if (lane < NW) aff_store(&swc[lane*12], w);
    }
    __syncthreads();
    if (wid > 0) sc = cmb(aff_load(&swc[(wid-1)*12]), sc);   // inclusive
    Aff E = aff_shfl_up(sc, 1);                               // exclusive
    if (lane == 0 && wid > 0) E = aff_load(&swc[(wid-1)*12]);

    Aff s0 = frame0(mc);
    Aff run = (tid == 0) ? s0 : cmb(s0, E);
#pragma unroll
    for (int i = 0; i < EPT; i++) {
        int j = e0 + i;
        if (j < nb) {
            Aff bp = run;
            reortho(bp);
            aff_store(&g_basePrefix[j*12], bp);
            run = cmb(run, aff_load(&g_blockComp[j*12]));
        }
    }
    if (tid == 0) g_ctr = 0;               // reset for next graph replay
}

// ---------------------------------------------------------------------------
// K3: stage, seed from prefix, vector walk with in-place float4 write-back,
//     coalesced scalar flush (out+9 is only 4B-aligned; conflict-free).
// ---------------------------------------------------------------------------
__global__ void __launch_bounds__(TPB) k3_emit(
        const float* __restrict__ inner, int n, int nchunks,
        float* __restrict__ out) {
    __shared__ float st[TPB * ROWF];
    int tid = threadIdx.x, b = blockIdx.x;
    int chunk = b * TPB + tid;

    long long tile0 = (long long)b * TILE_F;
    int nfl = (int)min((long long)TILE_F, (long long)n * 3 - tile0);
    stage_in(st, inner + tile0, nfl, tid);
    __syncthreads();

    if (chunk < nchunks) {
        Aff s = aff_load(&g_basePrefix[b*12]);
        if (tid > 0) {
            Aff pre;
#pragma unroll
            for (int c = 0; c < 9; c++) pre.m[c] = g_cs[c*MAXCHUNKS + chunk - 1];
#pragma unroll
            for (int c = 0; c < 3; c++) pre.t[c] = g_cs[(9+c)*MAXCHUNKS + chunk - 1];
            s = cmb(s, pre);
        }
        reortho(s);
        int base = chunk * C1;
        if (base + C1 <= n) {
            float4* row4 = (float4*)st + tid * ROW4;
#pragma unroll
            for (int G = 0; G < 4; G++) {
                float4 va = row4[3*G], vb = row4[3*G+1], vc = row4[3*G+2];
                float4 oa, ob, oc;
                chain_step(va.x, va.y, va.z, s); oa.x=s.t[0]; oa.y=s.t[1]; oa.z=s.t[2];
                chain_step(va.w, vb.x, vb.y, s); oa.w=s.t[0]; ob.x=s.t[1]; ob.y=s.t[2];
                chain_step(vb.z, vb.w, vc.x, s); ob.z=s.t[0]; ob.w=s.t[1]; oc.x=s.t[2];
                chain_step(vc.y, vc.z, vc.w, s); oc.y=s.t[0]; oc.z=s.t[1]; oc.w=s.t[2];
                row4[3*G] = oa; row4[3*G+1] = ob; row4[3*G+2] = oc;
            }
        } else {
            int lim = n - base;
            float* col = st + tid * ROWF;
            for (int k = 0; k < lim; k++) {
                chain_step(col[3*k], col[3*k+1], col[3*k+2], s);
                col[3*k]   = s.t[0];
                col[3*k+1] = s.t[1];
                col[3*k+2] = s.t[2];
            }
        }
    }
    __syncthreads();
    // coalesced scalar flush; q invariant across iterations (TPB % Q == 0)
    float* gout = out + 9 + tile0;
    int q0 = tid % Q, j0 = tid / Q;
#pragma unroll 8
    for (int f = tid; f < nfl; f += TPB) {
        gout[f] = st[j0*ROWF + q0];
        j0 += TPB/Q;
    }
}

extern "C" void kernel_launch(void* const* d_in, const int* in_sizes, int n_in,
                              void* d_out, int out_size) {
    const float* inner = (const float*)d_in[0];
    const float* mc    = (const float*)d_in[2];
    float* out = (float*)d_out;
    int n = in_sizes[0] / 3;
    int nchunks = (n + C1 - 1) / C1;              // 187500
    int nblocks = (nchunks + TPB - 1) / TPB;      // 977  (<= 1024)

    k1_chunks<<<nblocks, TPB>>>(inner, mc, out, n, nchunks, nblocks);
    k3_emit<<<nblocks, TPB>>>(inner, n, nchunks, out);
}

// round 10
// speedup vs baseline: 1.2192x; 1.0684x over previous
#include <cuda_runtime.h>
#include <cuda_bf16.h>
#include <cstdint>

// ============================================================================
// PNeRF coordinate extension as a chunked affine prefix scan (round 10).
// State (M, t): x_world = x_local @ M + t.  Step: M' = S M ; t' = t + bl*M'[0]
// Round 10: three-kernel R6 structure (fusion reverted), TWO-PHASE staging
//           (21.5KB smem/block) + 48-reg cap -> 7 blocks = 42 warps/SM.
// ============================================================================

#define C1    16                 // atoms per chunk (per thread)
#define TPB   192                // chunks per block (6 warps)
#define NW    (TPB/32)
#define QH    24                 // floats per chunk per phase (8 atoms)
#define ROWFH 28                 // padded floats per row per phase (112B)
#define ROW4H 7                  // float4 per row
#define TILE_F (TPB*C1*3)        // 9216 floats per block tile
#define MAXCHUNKS 188160
#define MAXBLK    1024

struct Aff { float m[9]; float t[3]; };

__device__ float g_cs[12 * MAXCHUNKS];          // chunkScan, SoA: [comp][chunk]
__device__ float g_blockComp[MAXBLK * 12];
__device__ float g_basePrefix[MAXBLK * 12];

// ---------------------------------------------------------------------------
// Accurate fp32 sincos (immune to --use_fast_math): Cody-Waite + Cephes polys.
// ---------------------------------------------------------------------------
__device__ __forceinline__ void fsincos(float x, float& s, float& c) {
    float q = rintf(x * 0.6366197723675814f);
    float r = fmaf(q, -1.5707963705062866f, x);
    r = fmaf(q, 4.37113883e-8f, r);
    int iq = (int)q;
    float z = r * r;
    float ps = fmaf(z, -1.9515295891e-4f, 8.3321608736e-3f);
    ps = fmaf(z, ps, -1.6666654611e-1f);
    float sr = fmaf(r * z, ps, r);
    float pc = fmaf(z, 2.443315711809948e-5f, -1.388731625493765e-3f);
    pc = fmaf(z, pc, 4.166664568298827e-2f);
    float cr = fmaf(z * z, pc, fmaf(z, -0.5f, 1.0f));
    bool sw = (iq & 1);
    float ss = sw ? cr : sr;
    float cc = sw ? sr : cr;
    if (iq & 2)        ss = -ss;
    if ((iq + 1) & 2)  cc = -cc;
    s = ss; c = cc;
}

// Theta path: bond_angle in [1.9, 2.1] -> Cody-Waite quadrant is always 1.
__device__ __forceinline__ void fsincos_th(float x, float& s, float& c) {
    float r = (x - 1.5707963705062866f) + 4.37113883e-8f;
    float z = r * r;
    float ps = fmaf(z, -1.9515295891e-4f, 8.3321608736e-3f);
    ps = fmaf(z, ps, -1.6666654611e-1f);
    float sr = fmaf(r * z, ps, r);
    float pc = fmaf(z, 2.443315711809948e-5f, -1.388731625493765e-3f);
    pc = fmaf(z, pc, 4.166664568298827e-2f);
    float cr = fmaf(z * z, pc, fmaf(z, -0.5f, 1.0f));
    s = cr; c = -sr;
}

__device__ __forceinline__ Aff aff_identity() {
    Aff a = {{1,0,0, 0,1,0, 0,0,1}, {0,0,0}};
    return a;
}

// Combine: A earlier (or state), B later composite.
__device__ __forceinline__ Aff cmb(const Aff& A, const Aff& B) {
    Aff r;
#pragma unroll
    for (int i = 0; i < 3; i++) {
        float b0 = B.m[3*i], b1 = B.m[3*i+1], b2 = B.m[3*i+2];
#pragma unroll
        for (int j = 0; j < 3; j++)
            r.m[3*i+j] = fmaf(b0, A.m[j], fmaf(b1, A.m[3+j], b2 * A.m[6+j]));
    }
#pragma unroll
    for (int j = 0; j < 3; j++)
        r.t[j] = fmaf(B.t[0], A.m[j], fmaf(B.t[1], A.m[3+j],
                 fmaf(B.t[2], A.m[6+j], A.t[j])));
    return r;
}

__device__ __forceinline__ void chain_step(float bl, float th, float ph, Aff& s) {
    float st, ct, sp, cp;
    fsincos_th(th, st, ct);
    fsincos(ph, sp, cp);
    float a = cp * st, b = sp * st, c = cp * ct, d = sp * ct;
#pragma unroll
    for (int j = 0; j < 3; j++) {
        float m0 = s.m[j], m1 = s.m[3+j], m2 = s.m[6+j];
        float r0 = fmaf(ct, m0, fmaf(a, m1, b * m2));
        float r1 = fmaf(c,  m1, fmaf(d, m2, -st * m0));
        float r2 = fmaf(cp, m2, -sp * m1);
        s.m[j] = r0; s.m[3+j] = r1; s.m[6+j] = r2;
        s.t[j] = fmaf(bl, r0, s.t[j]);
    }
}

// First step from identity: s = S, t = bl*S[0].
__device__ __forceinline__ void first_step(float bl, float th, float ph, Aff& s) {
    float st, ct, sp, cp;
    fsincos_th(th, st, ct);
    fsincos(ph, sp, cp);
    s.m[0] = ct;        s.m[1] = cp*st;  s.m[2] = sp*st;
    s.m[3] = -st;       s.m[4] = cp*ct;  s.m[5] = sp*ct;
    s.m[6] = 0.0f;      s.m[7] = -sp;    s.m[8] = cp;
    s.t[0] = bl*s.m[0]; s.t[1] = bl*s.m[1]; s.t[2] = bl*s.m[2];
}

__device__ __forceinline__ void reortho(Aff& s) {
    float inv = rsqrtf(fmaf(s.m[0], s.m[0], fmaf(s.m[1], s.m[1], s.m[2]*s.m[2])));
    s.m[0] *= inv; s.m[1] *= inv; s.m[2] *= inv;
    float d = fmaf(s.m[6], s.m[0], fmaf(s.m[7], s.m[1], s.m[8]*s.m[2]));
    s.m[6] = fmaf(-d, s.m[0], s.m[6]);
    s.m[7] = fmaf(-d, s.m[1], s.m[7]);
    s.m[8] = fmaf(-d, s.m[2], s.m[8]);
    inv = rsqrtf(fmaf(s.m[6], s.m[6], fmaf(s.m[7], s.m[7], s.m[8]*s.m[8])));
    s.m[6] *= inv; s.m[7] *= inv; s.m[8] *= inv;
    s.m[3] = s.m[7]*s.m[2] - s.m[8]*s.m[1];
    s.m[4] = s.m[8]*s.m[0] - s.m[6]*s.m[2];
    s.m[5] = s.m[6]*s.m[1] - s.m[7]*s.m[0];
}

__device__ __forceinline__ void aff_store(float* p, const Aff& a) {
#pragma unroll
    for (int i = 0; i < 9; i++) p[i] = a.m[i];
#pragma unroll
    for (int i = 0; i < 3; i++) p[9+i] = a.t[i];
}
__device__ __forceinline__ Aff aff_load(const float* p) {
    Aff a;
#pragma unroll
    for (int i = 0; i < 9; i++) a.m[i] = p[i];
#pragma unroll
    for (int i = 0; i < 3; i++) a.t[i] = p[9+i];
    return a;
}

__device__ __forceinline__ Aff aff_shfl_up(const Aff& a, int delta) {
    Aff r;
#pragma unroll
    for (int i = 0; i < 9; i++) r.m[i] = __shfl_up_sync(0xffffffffu, a.m[i], delta);
#pragma unroll
    for (int i = 0; i < 3; i++) r.t[i] = __shfl_up_sync(0xffffffffu, a.t[i], delta);
    return r;
}

// Stage one 24-float phase of every chunk: st[j*ROWFH + q], q in [0,24).
// Full-tile path: float4, division-free (chunk j's phase-p float4s are
// global float4 [j*12 + 6p, j*12 + 6p + 6)).
__device__ __forceinline__ void stage_phase_full(float* st, const float* __restrict__ gin,
                                                  int p, int tid) {
    const float4* g4 = (const float4*)gin;
    float4* s4 = (float4*)st;
    int k0 = tid % 6, j0 = tid / 6;
    int src = j0*12 + p*6 + k0;
    int dst = j0*ROW4H + k0;
#pragma unroll
    for (int it = 0; it < 6; it++) {       // 6*192 = 1152 float4 per phase
        s4[dst] = g4[src];
        src += 32*12;
        dst += 32*ROW4H;
    }
}
__device__ __forceinline__ void stage_phase_part(float* st, const float* __restrict__ gin,
                                                  int nfl, int p, int tid) {
    int q0 = tid % QH, j0 = tid / QH;
#pragma unroll 4
    for (int it = 0; it < TPB*QH/TPB; it++) {   // 24
        int j = j0 + (TPB/QH)*it;
        int f = j*48 + p*24 + q0;
        if (f < nfl) st[j*ROWFH + q0] = gin[f];
    }
}

// ---------------------------------------------------------------------------
// K1: two-phase stage+walk, block scan (shuffle), SoA chunk-scan stores.
// ---------------------------------------------------------------------------
__global__ void __launch_bounds__(TPB, 7) k1_chunks(const float* __restrict__ inner,
                                                    int n, int nchunks) {
    __shared__ float st[TPB * ROWFH];    // 21504 B
    __shared__ float swc[NW * 12];
    int tid = threadIdx.x, b = blockIdx.x;
    int lane = tid & 31, wid = tid >> 5;
    int chunk = b * TPB + tid;

    long long tile0 = (long long)b * TILE_F;
    int nfl = (int)min((long long)TILE_F, (long long)n * 3 - tile0);
    bool fullTile = (nfl == TILE_F);
    const float* gin = inner + tile0;
    int base = chunk * C1;
    int lim = (chunk < nchunks) ? min(C1, n - base) : 0;

    Aff s = aff_identity();
#pragma unroll
    for (int p = 0; p < 2; p++) {
        if (p) __syncthreads();            // walk of phase 0 done before restage
        if (fullTile) stage_phase_full(st, gin, p, tid);
        else          stage_phase_part(st, gin, nfl, p, tid);
        __syncthreads();
        if (fullTile ? (chunk < nchunks) : (lim > 8*p)) {
            if (fullTile) {
                const float4* row4 = (const float4*)st + tid * ROW4H;
                float4 va = row4[0], vb = row4[1], vc = row4[2];
                if (p == 0) first_step(va.x, va.y, va.z, s);
                else        chain_step(va.x, va.y, va.z, s);
                chain_step(va.w, vb.x, vb.y, s);
                chain_step(vb.z, vb.w, vc.x, s);
                chain_step(vc.y, vc.z, vc.w, s);
                va = row4[3]; vb = row4[4]; vc = row4[5];
                chain_step(va.x, va.y, va.z, s);
                chain_step(va.w, vb.x, vb.y, s);
                chain_step(vb.z, vb.w, vc.x, s);
                chain_step(vc.y, vc.z, vc.w, s);
            } else {
                const float* col = st + tid * ROWFH;
                int kEnd = min(lim, 8*p + 8);
                for (int k = 8*p; k < kEnd; k++) {
                    int kk = 3*(k - 8*p);
                    if (p == 0 && k == 0) first_step(col[0], col[1], col[2], s);
                    else chain_step(col[kk], col[kk+1], col[kk+2], s);
                }
            }
        }
    }
    // block scan (warp shuffle + cross-warp)
#pragma unroll
    for (int off = 1; off < 32; off <<= 1) {
        Aff p = aff_shfl_up(s, off);
        if (lane >= off) s = cmb(p, s);
    }
    if (lane == 31) aff_store(&swc[wid*12], s);
    __syncthreads();
    if (wid == 0) {
        Aff w = (lane < NW) ? aff_load(&swc[lane*12]) : aff_identity();
#pragma unroll
        for (int off = 1; off < NW; off <<= 1) {
            Aff p = aff_shfl_up(w, off);
            if (lane >= off) w = cmb(p, w);
        }
        if (lane < NW) aff_store(&swc[lane*12], w);
    }
    __syncthreads();
    if (wid > 0) s = cmb(aff_load(&swc[(wid-1)*12]), s);

    if (chunk < nchunks) {
#pragma unroll
        for (int c = 0; c < 9; c++)  g_cs[c*MAXCHUNKS + chunk] = s.m[c];
#pragma unroll
        for (int c = 0; c < 3; c++)  g_cs[(9+c)*MAXCHUNKS + chunk] = s.t[c];
    }
    if (tid == TPB - 1) aff_store(&g_blockComp[b*12], s);
}

// ---------------------------------------------------------------------------
// K2: scan block composites (hierarchical shuffle), seed with mainchain frame.
// ---------------------------------------------------------------------------
__global__ void __launch_bounds__(1024) k2_scan(int nb, const float* __restrict__ mc,
                                                float* __restrict__ out) {
    __shared__ float swc[32 * 12];
    __shared__ float s0sh[12];
    int tid = threadIdx.x, lane = tid & 31, wid = tid >> 5;
    if (tid == 0) {
        float Ax = mc[0], Ay = mc[1], Az = mc[2];
        float Bx = mc[3], By = mc[4], Bz = mc[5];
        float Cx = mc[6], Cy = mc[7], Cz = mc[8];
        float bx = Cx-Bx, by = Cy-By, bz = Cz-Bz;
        float inv = rsqrtf(bx*bx + by*by + bz*bz);
        bx *= inv; by *= inv; bz *= inv;
        float ux = Bx-Ax, uy = By-Ay, uz = Bz-Az;
        float nx = uy*bz - uz*by, ny = uz*bx - ux*bz, nz = ux*by - uy*bx;
        inv = rsqrtf(nx*nx + ny*ny + nz*nz);
        nx *= inv; ny *= inv; nz *= inv;
        s0sh[0]=bx; s0sh[1]=by; s0sh[2]=bz;
        s0sh[3]=ny*bz - nz*by; s0sh[4]=nz*bx - nx*bz; s0sh[5]=nx*by - ny*bx;
        s0sh[6]=nx; s0sh[7]=ny; s0sh[8]=nz;
        s0sh[9]=Cx; s0sh[10]=Cy; s0sh[11]=Cz;
    }
    if (tid < 9) out[tid] = mc[tid];
    Aff s = (tid < nb) ? aff_load(&g_blockComp[tid*12]) : aff_identity();
#pragma unroll
    for (int off = 1; off < 32; off <<= 1) {
        Aff p = aff_shfl_up(s, off);
        if (lane >= off) s = cmb(p, s);
    }
    if (lane == 31) aff_store(&swc[wid*12], s);
    __syncthreads();
    if (wid == 0) {
        Aff w = aff_load(&swc[lane*12]);
#pragma unroll
        for (int off = 1; off < 32; off <<= 1) {
            Aff p = aff_shfl_up(w, off);
            if (lane >= off) w = cmb(p, w);
        }
        aff_store(&swc[lane*12], w);
    }
    __syncthreads();
    if (wid > 0) s = cmb(aff_load(&swc[(wid-1)*12]), s);  // full inclusive
    Aff e = aff_shfl_up(s, 1);                             // exclusive prefix
    if (lane == 0 && wid > 0) e = aff_load(&swc[(wid-1)*12]);
    if (tid < nb) {
        Aff s0 = aff_load(s0sh);
        Aff bp = (tid == 0) ? s0 : cmb(s0, e);
        reortho(bp);
        aff_store(&g_basePrefix[tid*12], bp);
    }
}

// ---------------------------------------------------------------------------
// K3: two-phase: stage, walk with in-place float4 write-back, flush per phase.
// ---------------------------------------------------------------------------
__global__ void __launch_bounds__(TPB, 7) k3_emit(const float* __restrict__ inner,
                                                  int n, int nchunks,
                                                  float* __restrict__ out) {
    __shared__ float st[TPB * ROWFH];
    int tid = threadIdx.x, b = blockIdx.x;
    int chunk = b * TPB + tid;

    long long tile0 = (long long)b * TILE_F;
    int nfl = (int)min((long long)TILE_F, (long long)n * 3 - tile0);
    bool fullTile = (nfl == TILE_F);
    const float* gin = inner + tile0;
    float* gout = out + 9 + tile0;
    int base = chunk * C1;
    int lim = (chunk < nchunks) ? min(C1, n - base) : 0;

    Aff s;
    if (chunk < nchunks) {
        s = aff_load(&g_basePrefix[b*12]);
        if (tid > 0) {
            Aff pre;
#pragma unroll
            for (int c = 0; c < 9; c++) pre.m[c] = g_cs[c*MAXCHUNKS + chunk - 1];
#pragma unroll
            for (int c = 0; c < 3; c++) pre.t[c] = g_cs[(9+c)*MAXCHUNKS + chunk - 1];
            s = cmb(s, pre);
        }
        reortho(s);
    }

#pragma unroll
    for (int p = 0; p < 2; p++) {
        if (p) __syncthreads();            // flush of phase 0 done before restage
        if (fullTile) stage_phase_full(st, gin, p, tid);
        else          stage_phase_part(st, gin, nfl, p, tid);
        __syncthreads();
        if (fullTile ? (chunk < nchunks) : (lim > 8*p)) {
            if (fullTile) {
                float4* row4 = (float4*)st + tid * ROW4H;
#pragma unroll
                for (int G = 0; G < 2; G++) {
                    float4 va = row4[3*G], vb = row4[3*G+1], vc = row4[3*G+2];
                    float4 oa, ob, oc;
                    chain_step(va.x, va.y, va.z, s); oa.x=s.t[0]; oa.y=s.t[1]; oa.z=s.t[2];
                    chain_step(va.w, vb.x, vb.y, s); oa.w=s.t[0]; ob.x=s.t[1]; ob.y=s.t[2];
                    chain_step(vb.z, vb.w, vc.x, s); ob.z=s.t[0]; ob.w=s.t[1]; oc.x=s.t[2];
                    chain_step(vc.y, vc.z, vc.w, s); oc.y=s.t[0]; oc.z=s.t[1]; oc.w=s.t[2];
                    row4[3*G] = oa; row4[3*G+1] = ob; row4[3*G+2] = oc;
                }
            } else {
                float* col = st + tid * ROWFH;
                int kEnd = min(lim, 8*p + 8);
                for (int k = 8*p; k < kEnd; k++) {
                    int kk = 3*(k - 8*p);
                    chain_step(col[kk], col[kk+1], col[kk+2], s);
                    col[kk] = s.t[0]; col[kk+1] = s.t[1]; col[kk+2] = s.t[2];
                }
            }
        }
        __syncthreads();
        // flush phase p: global float j*48 + 24p + q  <-  st[j*ROWFH + q]
        {
            int q0 = tid % QH, j0 = tid / QH;
            if (fullTile) {
#pragma unroll 4
                for (int it = 0; it < TPB*QH/TPB; it++) {   // 24
                    int j = j0 + (TPB/QH)*it;
                    gout[j*48 + p*24 + q0] = st[j*ROWFH + q0];
                }
            } else {
#pragma unroll 4
                for (int it = 0; it < TPB*QH/TPB; it++) {
                    int j = j0 + (TPB/QH)*it;
                    int f = j*48 + p*24 + q0;
                    if (f < nfl) gout[f] = st[j*ROWFH + q0];
                }
            }
        }
    }
}

extern "C" void kernel_launch(void* const* d_in, const int* in_sizes, int n_in,
                              void* d_out, int out_size) {
    const float* inner = (const float*)d_in[0];
    const float* mc    = (const float*)d_in[2];
    float* out = (float*)d_out;
    int n = in_sizes[0] / 3;
    int nchunks = (n + C1 - 1) / C1;              // 187500
    int nblocks = (nchunks + TPB - 1) / TPB;      // 977  (<= 1024)

    k1_chunks<<<nblocks, TPB>>>(inner, n, nchunks);
    k2_scan<<<1, 1024>>>(nblocks, mc, out);
    k3_emit<<<nblocks, TPB>>>(inner, n, nchunks, out);
}